// round 13
// baseline (speedup 1.0000x reference)
#include <cuda_runtime.h>
#include <cuda_bf16.h>
#include <math.h>
#include <stdint.h>

#define BBATCH 32
#define SSEQ   512

// ---------------- device scratch ----------------
__device__ float g_hln [SSEQ * BBATCH * 1024];   // layernorm(E[x]), row m = s*32+b
__device__ float g_xc  [SSEQ * BBATCH * 1024];   // silu(conv), row m = s*32+b
__device__ float g_Wx  [67108864];               // [s][n][g][e][b]
__device__ float g_hlast[BBATCH * 1024];         // recurrence h at s=S-1, [b][n*256+e]
__device__ float g_hres [BBATCH * 1024];         // h1 = E[x_last] + mh_ln(hlast)
__device__ float g_ln2  [BBATCH * 1024];         // ln2(h1), [b][d]
__device__ float g_mid  [1344 * BBATCH];         // gelu(gate)*up, [j][b]

// ---------------- helpers ----------------
__device__ __forceinline__ unsigned long long fma2(unsigned long long a,
                                                   unsigned long long b,
                                                   unsigned long long c) {
    asm("fma.rn.f32x2 %0, %1, %2, %0;" : "+l"(c) : "l"(a), "l"(b));
    return c;
}
__device__ __forceinline__ unsigned long long add2(unsigned long long a,
                                                   unsigned long long b) {
    unsigned long long c;
    asm("add.rn.f32x2 %0, %1, %2;" : "=l"(c) : "l"(a), "l"(b));
    return c;
}
__device__ __forceinline__ unsigned long long packdup(float x) {
    unsigned long long r; unsigned u = __float_as_uint(x);
    asm("mov.b64 %0, {%1, %1};" : "=l"(r) : "r"(u));
    return r;
}
__device__ __forceinline__ float2 unpack2(unsigned long long v) {
    unsigned lo, hi;
    asm("mov.b64 {%0, %1}, %2;" : "=r"(lo), "=r"(hi) : "l"(v));
    return make_float2(__uint_as_float(lo), __uint_as_float(hi));
}
__device__ __forceinline__ uint32_t s2u(const void* p) {
    uint32_t a;
    asm("{.reg .u64 t; cvta.to.shared.u64 t, %1; cvt.u32.u64 %0, t;}" : "=r"(a) : "l"(p));
    return a;
}
__device__ __forceinline__ float2 blockReduce2(float a, float b) {
    __shared__ float sA[32], sB[32];
    #pragma unroll
    for (int o = 16; o; o >>= 1) {
        a += __shfl_xor_sync(0xffffffffu, a, o);
        b += __shfl_xor_sync(0xffffffffu, b, o);
    }
    int w = threadIdx.x >> 5, l = threadIdx.x & 31;
    int nw = (blockDim.x + 31) >> 5;
    __syncthreads();
    if (l == 0) { sA[w] = a; sB[w] = b; }
    __syncthreads();
    if (w == 0) {
        a = (l < nw) ? sA[l] : 0.f;
        b = (l < nw) ? sB[l] : 0.f;
        #pragma unroll
        for (int o = 16; o; o >>= 1) {
            a += __shfl_xor_sync(0xffffffffu, a, o);
            b += __shfl_xor_sync(0xffffffffu, b, o);
        }
        if (l == 0) { sA[0] = a; sB[0] = b; }
    }
    __syncthreads();
    return make_float2(sA[0], sB[0]);
}

// ---------------- K1: embedding + layernorm(ln1_w) ----------------
__global__ void __launch_bounds__(256) k_embed(const int* __restrict__ x,
                                               const float* __restrict__ E,
                                               const float* __restrict__ w) {
    int m = blockIdx.x, s = m >> 5, b = m & 31;
    int tok = x[b * SSEQ + s];
    float4 v = ((const float4*)(E + (size_t)tok * 1024))[threadIdx.x];
    float2 r = blockReduce2(v.x + v.y + v.z + v.w,
                            v.x*v.x + v.y*v.y + v.z*v.z + v.w*v.w);
    float mu = r.x * (1.f / 1024.f);
    float var = r.y * (1.f / 1024.f) - mu * mu;
    float inv = rsqrtf(var + 1e-5f);
    float4 ww = ((const float4*)w)[threadIdx.x];
    float4 o;
    o.x = (v.x - mu) * inv * ww.x;
    o.y = (v.y - mu) * inv * ww.y;
    o.z = (v.z - mu) * inv * ww.z;
    o.w = (v.w - mu) * inv * ww.w;
    ((float4*)(g_hln + (size_t)m * 1024))[threadIdx.x] = o;
}

// ---------------- K2: causal depthwise conv (K=4) + silu ----------------
__global__ void __launch_bounds__(256) k_conv(const float* __restrict__ cw,
                                              const float* __restrict__ cb) {
    int m = blockIdx.x, s = m >> 5, b = m & 31;
    int d0 = threadIdx.x * 4;
    const float4* cw4 = (const float4*)cw;
    float4 w0 = cw4[d0], w1 = cw4[d0 + 1], w2 = cw4[d0 + 2], w3 = cw4[d0 + 3];
    float W0[4] = {w0.x, w0.y, w0.z, w0.w};
    float W1[4] = {w1.x, w1.y, w1.z, w1.w};
    float W2[4] = {w2.x, w2.y, w2.z, w2.w};
    float W3[4] = {w3.x, w3.y, w3.z, w3.w};
    float a0 = cb[d0], a1 = cb[d0+1], a2 = cb[d0+2], a3 = cb[d0+3];
    #pragma unroll
    for (int k = 0; k < 4; k++) {
        int sp = s - 3 + k;
        if (sp >= 0) {
            float4 hv = *(const float4*)(g_hln + (size_t)(sp * 32 + b) * 1024 + d0);
            a0 = fmaf(hv.x, W0[k], a0);
            a1 = fmaf(hv.y, W1[k], a1);
            a2 = fmaf(hv.z, W2[k], a2);
            a3 = fmaf(hv.w, W3[k], a3);
        }
    }
    float4 o;
    o.x = a0 / (1.f + expf(-a0));
    o.y = a1 / (1.f + expf(-a1));
    o.z = a2 / (1.f + expf(-a2));
    o.w = a3 / (1.f + expf(-a3));
    *(float4*)(g_xc + (size_t)m * 1024 + d0) = o;
}

// ---------------- K3: gate GEMMs, C[m][e] = A[m][n*256+d] * Wg[g][n][d][e] ----------------
// grid (128, 4, 16=n*4+g), block 256. Output g_Wx[s][n][g][e][b].
__global__ void __launch_bounds__(256) k_gates(const float* __restrict__ Wg) {
    int n = blockIdx.z >> 2, g = blockIdx.z & 3;
    const float* A  = (g < 2) ? g_xc : g_hln;
    const float* Bm = Wg + (size_t)(g * 4 + n) * 65536;
    int m0 = blockIdx.x * 128, e0 = blockIdx.y * 64;
    __shared__ float As[16][136];
    __shared__ float Bs[16][64];
    int tid = threadIdx.x, tm = tid >> 4, tn = tid & 15;
    unsigned long long acc[8][2];
    #pragma unroll
    for (int i = 0; i < 8; i++) { acc[i][0] = 0ull; acc[i][1] = 0ull; }
    int lm = tid >> 1, lk = (tid & 1) * 8;
    int bk = tid >> 4, be = (tid & 15) * 4;
    const float* ap = A  + (size_t)(m0 + lm) * 1024 + n * 256 + lk;
    const float* bp = Bm + (size_t)bk * 256 + e0 + be;
    for (int kt = 0; kt < 256; kt += 16) {
        float4 a0 = *(const float4*)(ap + kt);
        float4 a1 = *(const float4*)(ap + kt + 4);
        float4 b4 = *(const float4*)(bp + (size_t)kt * 256);
        __syncthreads();
        As[lk+0][lm] = a0.x; As[lk+1][lm] = a0.y;
        As[lk+2][lm] = a0.z; As[lk+3][lm] = a0.w;
        As[lk+4][lm] = a1.x; As[lk+5][lm] = a1.y;
        As[lk+6][lm] = a1.z; As[lk+7][lm] = a1.w;
        *(float4*)&Bs[bk][be] = b4;
        __syncthreads();
        #pragma unroll
        for (int k = 0; k < 16; k++) {
            float4 x0 = *(const float4*)&As[k][tm * 8];
            float4 x1 = *(const float4*)&As[k][tm * 8 + 4];
            ulonglong2 y = *(const ulonglong2*)&Bs[k][tn * 4];
            float xs[8] = {x0.x, x0.y, x0.z, x0.w, x1.x, x1.y, x1.z, x1.w};
            #pragma unroll
            for (int i = 0; i < 8; i++) {
                unsigned long long xd = packdup(xs[i]);
                acc[i][0] = fma2(xd, y.x, acc[i][0]);
                acc[i][1] = fma2(xd, y.y, acc[i][1]);
            }
        }
    }
    int mrow = m0 + tm * 8, sI = mrow >> 5, b0 = mrow & 31;
    float av[8][4];
    #pragma unroll
    for (int i = 0; i < 8; i++) {
        float2 p0 = unpack2(acc[i][0]), p1 = unpack2(acc[i][1]);
        av[i][0] = p0.x; av[i][1] = p0.y; av[i][2] = p1.x; av[i][3] = p1.y;
    }
    size_t base = (((size_t)sI * 4 + n) * 4 + g) * 256;
    #pragma unroll
    for (int j = 0; j < 4; j++) {
        int e = e0 + tn * 4 + j;
        float* p = g_Wx + (base + e) * 32 + b0;
        *(float4*)p       = make_float4(av[0][j], av[1][j], av[2][j], av[3][j]);
        *(float4*)(p + 4) = make_float4(av[4][j], av[5][j], av[6][j], av[7][j]);
    }
}

// ---------------- K4: sLSTM recurrence, 8-CTA clusters ----------------
// grid 128, cluster 8. cluster cid=(n, bg of 8 batches); CTA rank owns e-slice 32.
// SMEM: Rs[128 go][258] | hp[2][256 d][8 b] | rawS[128][8] | hnS[32][8]
__global__ void __launch_bounds__(256, 1) __cluster_dims__(8, 1, 1)
k_recur(const float* __restrict__ R, const float* __restrict__ Rb) {
    extern __shared__ float sm[];
    float* Rs   = sm;
    float* hp   = sm + 33024;
    float* rawS = sm + 37120;
    float* hnS  = sm + 38144;
    int tid = threadIdx.x;
    uint32_t rank;
    asm("mov.u32 %0, %%cluster_ctarank;" : "=r"(rank));
    int cid = blockIdx.x >> 3, n = cid >> 2, bg = cid & 3;

    for (int i = tid; i < 128 * 258; i += 256) {
        int go = i / 258, d = i - go * 258;
        if (d < 256) {
            int g = go >> 5, e = go & 31;
            Rs[i] = R[(((size_t)n * 256 + d) * 4 + g) * 256 + rank * 32 + e];
        }
    }
    for (int i = tid; i < 4096; i += 256) hp[i] = 0.f;
    __syncthreads();
    asm volatile("barrier.cluster.arrive.aligned;\n\tbarrier.cluster.wait.aligned;" ::: "memory");

    int u = tid >> 1, hf = tid & 1;
    int g = u >> 5, e = u & 31;
    float rb = Rb[((size_t)g * 4 + n) * 256 + rank * 32 + e];
    int ge = tid >> 3, gb = tid & 7;       // gate-thread identity (e, b)
    float stC = 0.f, stN = 0.f, stM = 0.f;
    const float* RsU = Rs + u * 258 + hf;
    uint32_t hpb = s2u(hp);

    for (int t = 0; t < 512; t++) {
        int cur = t & 1, nxt = cur ^ 1;
        float4 wxa, wxb;
        if (hf == 0) {
            const float4* wp = (const float4*)(g_Wx +
                ((((size_t)t * 4 + n) * 4 + g) * 256 + rank * 32 + e) * 32 + bg * 8);
            wxa = wp[0]; wxb = wp[1];
        }
        unsigned long long a0 = 0, a1 = 0, a2 = 0, a3 = 0;
        const ulonglong2* hpc = (const ulonglong2*)(hp + cur * 2048);
        #pragma unroll 4
        for (int i = 0; i < 128; i++) {
            int d = 2 * i + hf;
            unsigned long long rv = packdup(RsU[2 * i]);
            ulonglong2 h01 = hpc[2 * d];
            ulonglong2 h23 = hpc[2 * d + 1];
            a0 = fma2(rv, h01.x, a0);
            a1 = fma2(rv, h01.y, a1);
            a2 = fma2(rv, h23.x, a2);
            a3 = fma2(rv, h23.y, a3);
        }
        a0 = add2(a0, __shfl_xor_sync(0xffffffffu, a0, 1));
        a1 = add2(a1, __shfl_xor_sync(0xffffffffu, a1, 1));
        a2 = add2(a2, __shfl_xor_sync(0xffffffffu, a2, 1));
        a3 = add2(a3, __shfl_xor_sync(0xffffffffu, a3, 1));
        if (hf == 0) {
            float2 p0 = unpack2(a0), p1 = unpack2(a1), p2 = unpack2(a2), p3 = unpack2(a3);
            float2* rw = (float2*)(rawS + u * 8);
            rw[0] = make_float2(p0.x + wxa.x + rb, p0.y + wxa.y + rb);
            rw[1] = make_float2(p1.x + wxa.z + rb, p1.y + wxa.w + rb);
            rw[2] = make_float2(p2.x + wxb.x + rb, p2.y + wxb.y + rb);
            rw[3] = make_float2(p3.x + wxb.z + rb, p3.y + wxb.w + rb);
        }
        __syncthreads();
        {
            float ir  = rawS[(0 * 32 + ge) * 8 + gb];
            float fr  = rawS[(1 * 32 + ge) * 8 + gb];
            float zr  = rawS[(2 * 32 + ge) * 8 + gb];
            float orr = rawS[(3 * 32 + ge) * 8 + gb];
            float lf  = (fr >= 0.f) ? -log1pf(expf(-fr)) : (fr - log1pf(expf(fr)));
            float lfm = stM + lf;
            float mn  = (t == 0) ? ir : fmaxf(ir, lfm);
            float ig  = expf(ir - mn), fg = expf(lfm - mn);
            stC = fg * stC + ig * tanhf(zr);
            stN = fg * stN + ig;
            stM = mn;
            float hv = stC / stN * (1.f / (1.f + expf(-orr)));
            hnS[ge * 8 + gb] = hv;
            if (t == 511)
                g_hlast[(bg * 8 + gb) * 1024 + n * 256 + rank * 32 + ge] = hv;
        }
        __syncthreads();
        if (tid < 64) {
            float4 v = ((float4*)hnS)[tid];
            uint32_t dst = hpb + (nxt * 2048 + rank * 256 + tid * 4) * 4;
            #pragma unroll
            for (int r = 0; r < 8; r++) {
                uint32_t ra;
                asm("mapa.shared::cluster.u32 %0, %1, %2;" : "=r"(ra) : "r"(dst), "r"(r));
                asm volatile("st.shared::cluster.v4.f32 [%0], {%1,%2,%3,%4};"
                             :: "r"(ra), "f"(v.x), "f"(v.y), "f"(v.z), "f"(v.w) : "memory");
            }
        }
        asm volatile("barrier.cluster.arrive.aligned;\n\tbarrier.cluster.wait.aligned;" ::: "memory");
    }
}

// ---------------- K5: per-head LN + residual + ln2 (last step only, 32 rows) ----------------
__global__ void __launch_bounds__(256) k_tail1(const int* __restrict__ x,
                                               const float* __restrict__ E,
                                               const float* __restrict__ gnw,
                                               const float* __restrict__ ln2w) {
    int b = blockIdx.x, t = threadIdx.x;
    float4 hv = ((const float4*)(g_hlast + b * 1024))[t];
    int head = t >> 6;
    float s1 = hv.x + hv.y + hv.z + hv.w;
    float s2 = hv.x*hv.x + hv.y*hv.y + hv.z*hv.z + hv.w*hv.w;
    #pragma unroll
    for (int o = 16; o; o >>= 1) {
        s1 += __shfl_xor_sync(0xffffffffu, s1, o);
        s2 += __shfl_xor_sync(0xffffffffu, s2, o);
    }
    __shared__ float w1[8], w2[8];
    int wid = t >> 5, l = t & 31;
    if (l == 0) { w1[wid] = s1; w2[wid] = s2; }
    __syncthreads();
    float mu  = (w1[head * 2] + w1[head * 2 + 1]) * (1.f / 256.f);
    float var = (w2[head * 2] + w2[head * 2 + 1]) * (1.f / 256.f) - mu * mu;
    float inv = rsqrtf(var + 1e-5f);
    float4 gw = ((const float4*)gnw)[t];
    int tok = x[b * SSEQ + (SSEQ - 1)];
    float4 ev = ((const float4*)(E + (size_t)tok * 1024))[t];
    float4 h1;
    h1.x = ev.x + (hv.x - mu) * inv * gw.x;
    h1.y = ev.y + (hv.y - mu) * inv * gw.y;
    h1.z = ev.z + (hv.z - mu) * inv * gw.z;
    h1.w = ev.w + (hv.w - mu) * inv * gw.w;
    ((float4*)(g_hres + b * 1024))[t] = h1;
    float2 r = blockReduce2(h1.x + h1.y + h1.z + h1.w,
                            h1.x*h1.x + h1.y*h1.y + h1.z*h1.z + h1.w*h1.w);
    float mu2  = r.x * (1.f / 1024.f);
    float var2 = r.y * (1.f / 1024.f) - mu2 * mu2;
    float inv2 = rsqrtf(var2 + 1e-5f);
    float4 lw = ((const float4*)ln2w)[t];
    float4 o;
    o.x = (h1.x - mu2) * inv2 * lw.x;
    o.y = (h1.y - mu2) * inv2 * lw.y;
    o.z = (h1.z - mu2) * inv2 * lw.z;
    o.w = (h1.w - mu2) * inv2 * lw.w;
    ((float4*)(g_ln2 + b * 1024))[t] = o;
}

// ---------------- K6: ffn_up column j, gelu(gate)*up ----------------
__global__ void __launch_bounds__(256) k_ffn1(const float* __restrict__ fup) {
    int j = blockIdx.x, t = threadIdx.x;
    __shared__ float cg[1024], cu[1024];
    for (int d = t; d < 1024; d += 256) {
        cg[d] = fup[(size_t)d * 2688 + j];
        cu[d] = fup[(size_t)d * 2688 + 1344 + j];
    }
    __syncthreads();
    int b = t >> 3, l8 = t & 7;
    float ag = 0.f, au = 0.f;
    const float* ln = g_ln2 + b * 1024;
    for (int d = l8; d < 1024; d += 8) {
        float v = ln[d];
        ag = fmaf(v, cg[d], ag);
        au = fmaf(v, cu[d], au);
    }
    #pragma unroll
    for (int o = 4; o; o >>= 1) {
        ag += __shfl_down_sync(0xffffffffu, ag, o, 8);
        au += __shfl_down_sync(0xffffffffu, au, o, 8);
    }
    if (l8 == 0) {
        float gl = 0.5f * ag * (1.f + erff(ag * 0.7071067811865475f));
        g_mid[j * 32 + b] = gl * au;
    }
}

// ---------------- K7: ffn_down + residual + post-LN + fc + sigmoid ----------------
__global__ void __launch_bounds__(256) k_tail2(const float* __restrict__ fdn,
                                               const float* __restrict__ pw,
                                               const float* __restrict__ fcw,
                                               const float* __restrict__ fcb,
                                               float* __restrict__ out) {
    int b = blockIdx.x, t = threadIdx.x;
    __shared__ float ms[1344];
    for (int j = t; j < 1344; j += 256) ms[j] = g_mid[j * 32 + b];
    __syncthreads();
    float4 acc = ((const float4*)(g_hres + b * 1024))[t];
    int d4 = t * 4;
    #pragma unroll 4
    for (int j = 0; j < 1344; j++) {
        float mj = ms[j];
        float4 w = *(const float4*)(fdn + (size_t)j * 1024 + d4);
        acc.x = fmaf(mj, w.x, acc.x);
        acc.y = fmaf(mj, w.y, acc.y);
        acc.z = fmaf(mj, w.z, acc.z);
        acc.w = fmaf(mj, w.w, acc.w);
    }
    float2 r = blockReduce2(acc.x + acc.y + acc.z + acc.w,
                            acc.x*acc.x + acc.y*acc.y + acc.z*acc.z + acc.w*acc.w);
    float mu  = r.x * (1.f / 1024.f);
    float var = r.y * (1.f / 1024.f) - mu * mu;
    float inv = rsqrtf(var + 1e-5f);
    float4 p = ((const float4*)pw)[t];
    float4 f = ((const float4*)fcw)[t];
    float dotp = (acc.x - mu) * inv * p.x * f.x
               + (acc.y - mu) * inv * p.y * f.y
               + (acc.z - mu) * inv * p.z * f.z
               + (acc.w - mu) * inv * p.w * f.w;
    float2 rr = blockReduce2(dotp, 0.f);
    if (t == 0) out[b] = 1.f / (1.f + expf(-(rr.x + fcb[0])));
}

// ---------------- launch ----------------
extern "C" void kernel_launch(void* const* d_in, const int* in_sizes, int n_in,
                              void* d_out, int out_size) {
    const int*   x    = (const int*)  d_in[0];
    const float* E    = (const float*)d_in[1];
    const float* ln1w = (const float*)d_in[2];
    const float* cw   = (const float*)d_in[3];
    const float* cb   = (const float*)d_in[4];
    const float* Wg   = (const float*)d_in[5];
    const float* R    = (const float*)d_in[6];
    const float* Rb   = (const float*)d_in[7];
    const float* gnw  = (const float*)d_in[8];
    const float* ln2w = (const float*)d_in[9];
    const float* fup  = (const float*)d_in[10];
    const float* fdn  = (const float*)d_in[11];
    const float* pw   = (const float*)d_in[12];
    const float* fcw  = (const float*)d_in[13];
    const float* fcb  = (const float*)d_in[14];
    float* out = (float*)d_out;

    cudaFuncSetAttribute(k_recur, cudaFuncAttributeMaxDynamicSharedMemorySize, 153600);

    k_embed<<<16384, 256>>>(x, E, ln1w);
    k_conv <<<16384, 256>>>(cw, cb);
    dim3 g3(128, 4, 16);
    k_gates<<<g3, 256>>>(Wg);
    k_recur<<<128, 256, 153600>>>(R, Rb);
    k_tail1<<<32, 256>>>(x, E, gnw, ln2w);
    k_ffn1 <<<1344, 256>>>(fup);
    k_tail2<<<32, 256>>>(fdn, pw, fcw, fcb, out);
}